// round 1
// baseline (speedup 1.0000x reference)
#include <cuda_runtime.h>
#include <math.h>

#define DD 31
#define DIMV 32
#define MARGIN 0.85f

__device__ __forceinline__ float gelu_exact(float x) {
    // jax.nn.gelu(approximate=False): 0.5*x*(1+erf(x/sqrt(2)))
    return 0.5f * x * (1.0f + erff(x * 0.70710678118654752440f));
}

__device__ __forceinline__ float warp_sum(float v) {
#pragma unroll
    for (int o = 16; o; o >>= 1) v += __shfl_xor_sync(0xffffffffu, v, o);
    return v;
}

__global__ __launch_bounds__(256, 2)
void hypernet_kernel(const int* __restrict__ g_u, const int* __restrict__ g_r,
                     const int* __restrict__ g_v, const float* __restrict__ emb,
                     const float* __restrict__ bias_head, const float* __restrict__ bias_tail,
                     const float* __restrict__ head_rot_w, const float* __restrict__ head_boost_w,
                     const float* __restrict__ tail_rot_w, const float* __restrict__ tail_boost_w,
                     float* __restrict__ out, int N) {
    // Row i of s_wt/s_wh: [0..30] = gelu'd Householder vector w_i, [31] = 2/||w_i||^2
    __shared__ __align__(16) float s_wt[DD][DIMV];
    __shared__ __align__(16) float s_wh[DD][DIMV];
    __shared__ float s_th[DIMV];   // transformed head vector (time at [0])
    __shared__ float s_ro[DD];     // tail boost rapidity vector
    __shared__ float s_par[4];     // zeta_t, coef_t, tanh(bias_head[u])

    const int b    = blockIdx.x;
    const int tid  = threadIdx.x;
    const int lane = tid & 31;
    const int wid  = tid >> 5;
    const int rb   = g_r[b];

    // ---------------- Phase A: gelu both rotation tables into shared ----------------
    const float* hw = head_rot_w + (long)rb * (DD * DD);
    const float* tw = tail_rot_w + (long)rb * (DD * DD);
    for (int k = tid; k < DD * DD; k += blockDim.x) {
        int i = k / DD, j = k - i * DD;
        s_wh[i][j] = gelu_exact(hw[k]);
        s_wt[i][j] = gelu_exact(tw[k]);
    }
    __syncthreads();

    // ---------------- Phase A2: row norms (warps 0/1), tail boost (warp 2), bias (warp 3)
    if (wid == 0) {
#pragma unroll 1
        for (int i = 0; i < DD; i++) {
            float w  = (lane < DD) ? s_wt[i][lane] : 0.f;
            float n2 = warp_sum(w * w);
            if (lane == 0) s_wt[i][DD] = 2.0f / n2;
        }
    } else if (wid == 1) {
#pragma unroll 1
        for (int i = 0; i < DD; i++) {
            float w  = (lane < DD) ? s_wh[i][lane] : 0.f;
            float n2 = warp_sum(w * w);
            if (lane == 0) s_wh[i][DD] = 2.0f / n2;
        }
    } else if (wid == 2) {
        float ro = (lane < DD) ? tanhf(tail_boost_w[(long)rb * DD + lane]) * (1.0f / DIMV) : 0.f;
        if (lane < DD) s_ro[lane] = ro;
        float v2   = warp_sum(ro * ro);
        float zeta = 1.0f / (sqrtf(1.0f - v2) + 1e-8f);
        if (lane == 0) { s_par[0] = zeta; s_par[1] = (zeta - 1.0f) / (v2 + 1e-9f); }
    } else if (wid == 3) {
        if (lane == 0) s_par[2] = tanhf(bias_head[g_u[b]]);
    }
    __syncthreads();

    // ---------------- Phase B: warp 0 transforms the head vector ----------------
    if (wid == 0) {
        float c = emb[(long)g_u[b] * DIMV + lane];  // lane j holds component j (lane 0 = time)
#pragma unroll 1
        for (int i = 0; i < DD; i++) {
            float w   = (lane >= 1) ? s_wh[i][lane - 1] : 0.f;
            float sc  = s_wh[i][DD];
            float dot = warp_sum(c * w);
            c = fmaf(-sc * dot, w, c);
        }
        // head boost
        float rh   = (lane >= 1) ? tanhf(head_boost_w[(long)rb * DD + lane - 1]) * (1.0f / DIMV) : 0.f;
        float v2   = warp_sum(rh * rh);
        float zeta = 1.0f / (sqrtf(1.0f - v2) + 1e-8f);
        float coef = (zeta - 1.0f) / (v2 + 1e-9f);
        float tval = __shfl_sync(0xffffffffu, c, 0);
        float dotb = warp_sum(c * rh);  // lane 0 contributes 0 (rh=0 there)
        float res;
        if (lane == 0) res = zeta * tval - zeta * dotb;
        else           res = -zeta * tval * rh + c + coef * rh * dotb;
        s_th[lane] = res;
    }
    __syncthreads();

    const float zeta_t = s_par[0];
    const float coef_t = s_par[1];
    const float tbh    = s_par[2];

    // ---------------- Phase C: each thread handles one tail vector ----------------
    for (int n = tid; n < N; n += blockDim.x) {
        const int vi = g_v[(long)b * N + n];

        // load tail embedding (32 floats = 8 x float4, 128B-aligned rows)
        float x0, xr[DD];
        const float4* ep = (const float4*)(emb + (long)vi * DIMV);
        {
            float4 e = ep[0];
            x0 = e.x; xr[0] = e.y; xr[1] = e.z; xr[2] = e.w;
        }
#pragma unroll
        for (int q = 1; q < 8; q++) {
            float4 e = ep[q];
            xr[q * 4 - 1] = e.x; xr[q * 4] = e.y; xr[q * 4 + 1] = e.z; xr[q * 4 + 2] = e.w;
        }
        const float btail = bias_tail[vi];

        // 31 Householder reflections (tail rotation); time component untouched
#pragma unroll 1
        for (int i = 0; i < DD; i++) {
            const float4* wp = (const float4*)(&s_wt[i][0]);
            float wl[DIMV];
#pragma unroll
            for (int q = 0; q < 8; q++) {
                float4 wv = wp[q];
                wl[q * 4] = wv.x; wl[q * 4 + 1] = wv.y; wl[q * 4 + 2] = wv.z; wl[q * 4 + 3] = wv.w;
            }
            float a0 = 0.f, a1 = 0.f, a2 = 0.f, a3 = 0.f;
#pragma unroll
            for (int j = 0; j < 28; j += 4) {
                a0 = fmaf(xr[j], wl[j], a0);
                a1 = fmaf(xr[j + 1], wl[j + 1], a1);
                a2 = fmaf(xr[j + 2], wl[j + 2], a2);
                a3 = fmaf(xr[j + 3], wl[j + 3], a3);
            }
            a0 = fmaf(xr[28], wl[28], a0);
            a1 = fmaf(xr[29], wl[29], a1);
            a2 = fmaf(xr[30], wl[30], a2);
            float dot = (a0 + a1) + (a2 + a3);
            float g = wl[DD] * dot;  // (2/||w||^2) * dot
#pragma unroll
            for (int j = 0; j < DD; j++) xr[j] = fmaf(-g, wl[j], xr[j]);
        }

        // tail boost
        float b0 = 0.f, b1 = 0.f, b2 = 0.f, b3 = 0.f;
#pragma unroll
        for (int j = 0; j < 28; j += 4) {
            b0 = fmaf(xr[j], s_ro[j], b0);
            b1 = fmaf(xr[j + 1], s_ro[j + 1], b1);
            b2 = fmaf(xr[j + 2], s_ro[j + 2], b2);
            b3 = fmaf(xr[j + 3], s_ro[j + 3], b3);
        }
        b0 = fmaf(xr[28], s_ro[28], b0);
        b1 = fmaf(xr[29], s_ro[29], b1);
        b2 = fmaf(xr[30], s_ro[30], b2);
        const float dotb = (b0 + b1) + (b2 + b3);

        const float nx0 = zeta_t * x0 - zeta_t * dotb;
        const float d0  = nx0 - s_th[0];
        const float mzt = -zeta_t * x0;

        float acc = 0.f;
#pragma unroll
        for (int j = 0; j < DD; j++) {
            float ro = s_ro[j];
            float xn = fmaf(mzt, ro, xr[j]) + coef_t * ro * dotb;
            float dj = xn - s_th[j + 1];
            acc = fmaf(dj, dj, acc);
        }
        const float mkv = acc - d0 * d0;  // sum(d^2) - 2*d0^2

        out[(long)b * N + n] = MARGIN - mkv + tbh + tanhf(btail);
    }
}

extern "C" void kernel_launch(void* const* d_in, const int* in_sizes, int n_in,
                              void* d_out, int out_size) {
    const int*   u   = (const int*)d_in[0];
    const int*   r   = (const int*)d_in[1];
    const int*   v   = (const int*)d_in[2];
    const float* emb = (const float*)d_in[3];
    const float* bh  = (const float*)d_in[4];
    const float* bt  = (const float*)d_in[5];
    const float* hrw = (const float*)d_in[6];
    const float* hbw = (const float*)d_in[7];
    const float* trw = (const float*)d_in[8];
    const float* tbw = (const float*)d_in[9];
    float* out = (float*)d_out;

    const int B = in_sizes[0];
    const int N = in_sizes[2] / B;

    hypernet_kernel<<<B, 256>>>(u, r, v, emb, bh, bt, hrw, hbw, trw, tbw, out, N);
}